// round 1
// baseline (speedup 1.0000x reference)
#include <cuda_runtime.h>
#include <cuda_fp16.h>

#define D          128
#define TILE_R     64
#define NTHREADS   256
#define XS_STRIDE  66        // float2 stride for XsP/CsQ: padded (bank-conflict-free) and 16B-aligned

typedef unsigned long long u64;

// Packed dual-fp32 FMA: acc.lo += a.lo*b.lo ; acc.hi += a.hi*b.hi  (sm_100+ FFMA2)
__device__ __forceinline__ void fma2(u64 &acc, u64 a, u64 b) {
    asm("fma.rn.f32x2 %0, %1, %2, %0;" : "+l"(acc) : "l"(a), "l"(b));
}
__device__ __forceinline__ float f2lo(u64 v) { return __uint_as_float((unsigned)(v & 0xffffffffull)); }
__device__ __forceinline__ float f2hi(u64 v) { return __uint_as_float((unsigned)(v >> 32)); }

// Shared layout (float2 units):
//   PiP [64][128] : PiP[kp][j]  = (Pi[j][2kp],   Pi[j][2kp+1])   -- rotate operand (k-pair packed)
//   PiQ [64][128] : PiQ[jp][k]  = (Pi[2jp][k],   Pi[2jp+1][k])   -- unrotate operand (j-pair packed)
//   XsP [64][XS_STRIDE] : XsP[kp][r] = normalized x pairs (k-pair packed, row-minor)
//   CsQ [64][XS_STRIDE] : CsQ[jp][r] = centroid value pairs (j-pair packed, row-minor)
#define SMEM_F2   (64*128 + 64*128 + 64*XS_STRIDE + 64*XS_STRIDE)
#define SMEM_BYTES (SMEM_F2 * 8 + (TILE_R + 16) * 4)

__global__ void __launch_bounds__(NTHREADS, 1)
tq_kernel(const float* __restrict__ x, const float* __restrict__ Pi,
          const float* __restrict__ cent, const float* __restrict__ bnd,
          float* __restrict__ out, int n_rows, int ntiles)
{
    extern __shared__ float2 smem2[];
    float2* PiP = smem2;
    float2* PiQ = PiP + 64 * 128;
    float2* XsP = PiQ + 64 * 128;
    float2* CsQ = XsP + 64 * XS_STRIDE;
    float*  norm16_s = (float*)(CsQ + 64 * XS_STRIDE);   // [TILE_R]
    float*  cent_s   = norm16_s + TILE_R;                // [16]

    const int tid = threadIdx.x;

    // ---- one-time per block: pack Pi both ways, stage centroids ----
    for (int i = tid; i < 64 * 128; i += NTHREADS) {
        int a = i >> 7;        // kp (for PiP) / jp (for PiQ)
        int b = i & 127;       // j  (for PiP) / k  (for PiQ)
        PiP[i] = make_float2(Pi[b * 128 + 2 * a],     Pi[b * 128 + 2 * a + 1]);
        PiQ[i] = make_float2(Pi[(2 * a) * 128 + b],   Pi[(2 * a + 1) * 128 + b]);
    }
    if (tid < 16) cent_s[tid] = cent[tid];

    // inner boundaries b[1..15] in registers
    float breg[15];
    #pragma unroll
    for (int t = 0; t < 15; t++) breg[t] = bnd[t + 1];
    __syncthreads();

    const int ty = tid >> 4;           // 0..15 : row group
    const int tx = tid & 15;           // 0..15 : col group
    const int r0 = ty * 4;             // 4 rows per thread
    const int c0 = tx * 8;             // 8 cols per thread

    for (int tile = blockIdx.x; tile < ntiles; tile += gridDim.x) {

        // ================= phase 1: load, norm, normalize, pack =================
        {
            const int rl = tid >> 2;            // local row 0..63
            const int l  = tid & 3;             // 4 lanes per row (same warp)
            const int grow = tile * TILE_R + rl;
            float4 v[8];
            float ss = 0.0f;
            if (grow < n_rows) {
                const float* xr = x + (size_t)grow * D;
                #pragma unroll
                for (int c = 0; c < 8; c++) {
                    // lane l covers k = 16*c + 4*l .. +3 (interleaved: conflict-free smem stores)
                    v[c] = *(const float4*)(xr + 16 * c + 4 * l);
                    ss += v[c].x * v[c].x + v[c].y * v[c].y + v[c].z * v[c].z + v[c].w * v[c].w;
                }
            } else {
                #pragma unroll
                for (int c = 0; c < 8; c++) v[c] = make_float4(0.f, 0.f, 0.f, 0.f);
            }
            ss += __shfl_xor_sync(0xffffffffu, ss, 1);
            ss += __shfl_xor_sync(0xffffffffu, ss, 2);
            float nrm = __fsqrt_rn(ss);
            float den = nrm + 1e-8f;
            if (l == 0) norm16_s[rl] = __half2float(__float2half_rn(nrm));
            #pragma unroll
            for (int c = 0; c < 8; c++) {
                int k = 16 * c + 4 * l;
                float a0 = __fdiv_rn(v[c].x, den);
                float a1 = __fdiv_rn(v[c].y, den);
                float a2 = __fdiv_rn(v[c].z, den);
                float a3 = __fdiv_rn(v[c].w, den);
                XsP[(k >> 1)       * XS_STRIDE + rl] = make_float2(a0, a1);
                XsP[((k >> 1) + 1) * XS_STRIDE + rl] = make_float2(a2, a3);
            }
        }
        __syncthreads();

        // ================= GEMM1: rot[r][j] = sum_k xn[r][k] * Pi[j][k] =================
        u64 acc[4][8];
        #pragma unroll
        for (int i = 0; i < 4; i++)
            #pragma unroll
            for (int j = 0; j < 8; j++) acc[i][j] = 0ull;

        #pragma unroll 4
        for (int kp = 0; kp < 64; kp++) {
            u64 xv[4], pv[8];
            #pragma unroll
            for (int i = 0; i < 4; i++)
                xv[i] = *(const u64*)&XsP[kp * XS_STRIDE + r0 + i];
            #pragma unroll
            for (int j = 0; j < 8; j++)
                pv[j] = *(const u64*)&PiP[kp * 128 + c0 + j];
            #pragma unroll
            for (int i = 0; i < 4; i++)
                #pragma unroll
                for (int j = 0; j < 8; j++)
                    fma2(acc[i][j], xv[i], pv[j]);
        }

        // ================= quantize (searchsorted left) + centroid gather =================
        #pragma unroll
        for (int i = 0; i < 4; i++) {
            #pragma unroll
            for (int j2 = 0; j2 < 4; j2++) {
                float v0 = f2lo(acc[i][2 * j2])     + f2hi(acc[i][2 * j2]);
                float v1 = f2lo(acc[i][2 * j2 + 1]) + f2hi(acc[i][2 * j2 + 1]);
                int i0 = 0, i1 = 0;
                #pragma unroll
                for (int t = 0; t < 15; t++) {
                    i0 += (v0 > breg[t]);
                    i1 += (v1 > breg[t]);
                }
                CsQ[((c0 >> 1) + j2) * XS_STRIDE + r0 + i] =
                    make_float2(cent_s[i0], cent_s[i1]);
            }
        }
        __syncthreads();

        // ================= GEMM2: rec[r][k] = sum_j cval[r][j] * Pi[j][k] =================
        u64 oac[4][8];
        #pragma unroll
        for (int i = 0; i < 4; i++)
            #pragma unroll
            for (int j = 0; j < 8; j++) oac[i][j] = 0ull;

        #pragma unroll 4
        for (int jp = 0; jp < 64; jp++) {
            u64 cv[4], pv[8];
            #pragma unroll
            for (int i = 0; i < 4; i++)
                cv[i] = *(const u64*)&CsQ[jp * XS_STRIDE + r0 + i];
            #pragma unroll
            for (int j = 0; j < 8; j++)
                pv[j] = *(const u64*)&PiQ[jp * 128 + c0 + j];
            #pragma unroll
            for (int i = 0; i < 4; i++)
                #pragma unroll
                for (int j = 0; j < 8; j++)
                    fma2(oac[i][j], cv[i], pv[j]);
        }

        // ================= scale by fp16-rounded norm, store =================
        #pragma unroll
        for (int i = 0; i < 4; i++) {
            int grow = tile * TILE_R + r0 + i;
            if (grow < n_rows) {
                float s = norm16_s[r0 + i];
                float o[8];
                #pragma unroll
                for (int j = 0; j < 8; j++)
                    o[j] = (f2lo(oac[i][j]) + f2hi(oac[i][j])) * s;
                float4* op = (float4*)(out + (size_t)grow * D + c0);
                op[0] = make_float4(o[0], o[1], o[2], o[3]);
                op[1] = make_float4(o[4], o[5], o[6], o[7]);
            }
        }
        __syncthreads();   // protect norm16_s / XsP / CsQ before next tile's phase 1
    }
}

extern "C" void kernel_launch(void* const* d_in, const int* in_sizes, int n_in,
                              void* d_out, int out_size)
{
    const float* x    = (const float*)d_in[0];   // [B,H,S,128] fp32
    const float* Pi   = (const float*)d_in[1];   // [128,128]
    const float* cent = (const float*)d_in[2];   // [16]
    const float* bnd  = (const float*)d_in[3];   // [17]
    float* out = (float*)d_out;

    int n_rows = in_sizes[0] / D;
    int ntiles = (n_rows + TILE_R - 1) / TILE_R;

    cudaFuncSetAttribute(tq_kernel, cudaFuncAttributeMaxDynamicSharedMemorySize, SMEM_BYTES);

    int dev = 0, sms = 148;
    cudaGetDevice(&dev);
    cudaDeviceGetAttribute(&sms, cudaDevAttrMultiProcessorCount, dev);
    int grid = (ntiles < sms) ? ntiles : sms;   // persistent: one block per SM

    tq_kernel<<<grid, NTHREADS, SMEM_BYTES>>>(x, Pi, cent, bnd, out, n_rows, ntiles);
}

// round 2
// speedup vs baseline: 2.3462x; 2.3462x over previous
#include <cuda_runtime.h>
#include <cuda_fp16.h>

#define D          128
#define TILE_R     64
#define NTHREADS   256
#define XS_STRIDE  66        // float2 stride for XsP/CsQ: padded and 16B-aligned

typedef unsigned long long u64;

// Packed dual-fp32 FMA: acc.lo += a.lo*b.lo ; acc.hi += a.hi*b.hi  (sm_100+ FFMA2)
__device__ __forceinline__ void fma2(u64 &acc, u64 a, u64 b) {
    asm("fma.rn.f32x2 %0, %1, %2, %0;" : "+l"(acc) : "l"(a), "l"(b));
}
__device__ __forceinline__ float f2lo(u64 v) { return __uint_as_float((unsigned)(v & 0xffffffffull)); }
__device__ __forceinline__ float f2hi(u64 v) { return __uint_as_float((unsigned)(v >> 32)); }

// Shared layout (float2 units):
//   PiP [64][128] : PiP[kp][c]  = (Pi[c][2kp],   Pi[c][2kp+1])   -- rotate operand (k-pair packed)
//   PiQ [64][128] : PiQ[jp][k]  = (Pi[2jp][k],   Pi[2jp+1][k])   -- unrotate operand (j-pair packed)
//   XsP [64][XS_STRIDE] : XsP[kp][r] = normalized x pairs (k-pair packed, row-minor)
//   CsQ [64][XS_STRIDE] : CsQ[jp][r] = centroid value pairs (j-pair packed, row-minor)
#define SMEM_F2   (64*128 + 64*128 + 64*XS_STRIDE + 64*XS_STRIDE)
#define SMEM_BYTES (SMEM_F2 * 8 + (TILE_R + 16) * 4)

__global__ void __launch_bounds__(NTHREADS, 1)
tq_kernel(const float* __restrict__ x, const float* __restrict__ Pi,
          const float* __restrict__ cent, const float* __restrict__ bnd,
          float* __restrict__ out, int n_rows, int ntiles)
{
    extern __shared__ float2 smem2[];
    float2* PiP = smem2;
    float2* PiQ = PiP + 64 * 128;
    float2* XsP = PiQ + 64 * 128;
    float2* CsQ = XsP + 64 * XS_STRIDE;
    float*  CsQf = (float*)CsQ;
    float*  norm16_s = (float*)(CsQ + 64 * XS_STRIDE);   // [TILE_R]
    float*  cent_s   = norm16_s + TILE_R;                // [16]

    const int tid = threadIdx.x;

    // ---- one-time per block: pack Pi both ways, stage centroids ----
    for (int i = tid; i < 64 * 128; i += NTHREADS) {
        int a = i >> 7;        // kp (for PiP) / jp (for PiQ)
        int b = i & 127;       // c  (for PiP) / k  (for PiQ)
        PiP[i] = make_float2(Pi[b * 128 + 2 * a],     Pi[b * 128 + 2 * a + 1]);
        PiQ[i] = make_float2(Pi[(2 * a) * 128 + b],   Pi[(2 * a + 1) * 128 + b]);
    }
    if (tid < 16) cent_s[tid] = cent[tid];

    // inner boundaries b[1..15] in registers
    float breg[15];
    #pragma unroll
    for (int t = 0; t < 15; t++) breg[t] = bnd[t + 1];
    __syncthreads();

    const int ty = tid >> 4;           // 0..15 : row group
    const int tx = tid & 15;           // 0..15 : column lane
    const int r0 = ty * 4;             // 4 rows per thread
    // column ownership: c = tx + 16*jj, jj = 0..7 (interleaved: conflict-free LDS)

    for (int tile = blockIdx.x; tile < ntiles; tile += gridDim.x) {

        // ================= phase 1: load, norm, normalize, pack =================
        {
            const int rl = tid >> 2;            // local row 0..63
            const int l  = tid & 3;             // 4 lanes per row (same warp)
            const int grow = tile * TILE_R + rl;
            float4 v[8];
            float ss = 0.0f;
            if (grow < n_rows) {
                const float* xr = x + (size_t)grow * D;
                #pragma unroll
                for (int c = 0; c < 8; c++) {
                    v[c] = *(const float4*)(xr + 16 * c + 4 * l);
                    ss += v[c].x * v[c].x + v[c].y * v[c].y + v[c].z * v[c].z + v[c].w * v[c].w;
                }
            } else {
                #pragma unroll
                for (int c = 0; c < 8; c++) v[c] = make_float4(0.f, 0.f, 0.f, 0.f);
            }
            ss += __shfl_xor_sync(0xffffffffu, ss, 1);
            ss += __shfl_xor_sync(0xffffffffu, ss, 2);
            float nrm = __fsqrt_rn(ss);
            float den = nrm + 1e-8f;
            if (l == 0) norm16_s[rl] = __half2float(__float2half_rn(nrm));
            #pragma unroll
            for (int c = 0; c < 8; c++) {
                int k = 16 * c + 4 * l;
                float a0 = __fdiv_rn(v[c].x, den);
                float a1 = __fdiv_rn(v[c].y, den);
                float a2 = __fdiv_rn(v[c].z, den);
                float a3 = __fdiv_rn(v[c].w, den);
                XsP[(k >> 1)       * XS_STRIDE + rl] = make_float2(a0, a1);
                XsP[((k >> 1) + 1) * XS_STRIDE + rl] = make_float2(a2, a3);
            }
        }
        __syncthreads();

        // ================= GEMM1: rot[r][c] = sum_k xn[r][k] * Pi[c][k] =================
        u64 acc[4][8];
        #pragma unroll
        for (int i = 0; i < 4; i++)
            #pragma unroll
            for (int j = 0; j < 8; j++) acc[i][j] = 0ull;

        #pragma unroll 4
        for (int kp = 0; kp < 64; kp++) {
            u64 xv[4], pv[8];
            #pragma unroll
            for (int i = 0; i < 4; i++)
                xv[i] = *(const u64*)&XsP[kp * XS_STRIDE + r0 + i];
            #pragma unroll
            for (int jj = 0; jj < 8; jj++)
                pv[jj] = *(const u64*)&PiP[kp * 128 + tx + 16 * jj];
            #pragma unroll
            for (int i = 0; i < 4; i++)
                #pragma unroll
                for (int jj = 0; jj < 8; jj++)
                    fma2(acc[i][jj], xv[i], pv[jj]);
        }

        // ================= quantize (searchsorted left) + centroid gather =================
        #pragma unroll
        for (int i = 0; i < 4; i++) {
            #pragma unroll
            for (int jj = 0; jj < 8; jj++) {
                float v0 = f2lo(acc[i][jj]) + f2hi(acc[i][jj]);
                int i0 = 0;
                #pragma unroll
                for (int t = 0; t < 15; t++) i0 += (v0 > breg[t]);
                int c  = tx + 16 * jj;
                int cp = c >> 1;
                // scalar store into the (c&1) half of CsQ[cp][r0+i]
                CsQf[(cp * XS_STRIDE + r0 + i) * 2 + (c & 1)] = cent_s[i0];
            }
        }
        __syncthreads();

        // ================= GEMM2: rec[r][k] = sum_j cval[r][j] * Pi[j][k] =================
        u64 oac[4][8];
        #pragma unroll
        for (int i = 0; i < 4; i++)
            #pragma unroll
            for (int jj = 0; jj < 8; jj++) oac[i][jj] = 0ull;

        #pragma unroll 4
        for (int jp = 0; jp < 64; jp++) {
            u64 cv[4], pv[8];
            #pragma unroll
            for (int i = 0; i < 4; i++)
                cv[i] = *(const u64*)&CsQ[jp * XS_STRIDE + r0 + i];
            #pragma unroll
            for (int jj = 0; jj < 8; jj++)
                pv[jj] = *(const u64*)&PiQ[jp * 128 + tx + 16 * jj];
            #pragma unroll
            for (int i = 0; i < 4; i++)
                #pragma unroll
                for (int jj = 0; jj < 8; jj++)
                    fma2(oac[i][jj], cv[i], pv[jj]);
        }

        // ================= scale by fp16-rounded norm, store =================
        #pragma unroll
        for (int i = 0; i < 4; i++) {
            int grow = tile * TILE_R + r0 + i;
            if (grow < n_rows) {
                float s = norm16_s[r0 + i];
                float* op = out + (size_t)grow * D;
                #pragma unroll
                for (int jj = 0; jj < 8; jj++)
                    op[tx + 16 * jj] = (f2lo(oac[i][jj]) + f2hi(oac[i][jj])) * s;
            }
        }
        __syncthreads();   // protect norm16_s / XsP / CsQ before next tile's phase 1
    }
}

extern "C" void kernel_launch(void* const* d_in, const int* in_sizes, int n_in,
                              void* d_out, int out_size)
{
    const float* x    = (const float*)d_in[0];   // [B,H,S,128] fp32
    const float* Pi   = (const float*)d_in[1];   // [128,128]
    const float* cent = (const float*)d_in[2];   // [16]
    const float* bnd  = (const float*)d_in[3];   // [17]
    float* out = (float*)d_out;

    int n_rows = in_sizes[0] / D;
    int ntiles = (n_rows + TILE_R - 1) / TILE_R;

    cudaFuncSetAttribute(tq_kernel, cudaFuncAttributeMaxDynamicSharedMemorySize, SMEM_BYTES);

    int dev = 0, sms = 148;
    cudaGetDevice(&dev);
    cudaDeviceGetAttribute(&sms, cudaDevAttrMultiProcessorCount, dev);
    int grid = (ntiles < sms) ? ntiles : sms;   // persistent: one block per SM

    tq_kernel<<<grid, NTHREADS, SMEM_BYTES>>>(x, Pi, cent, bnd, out, n_rows, ntiles);
}